// round 17
// baseline (speedup 1.0000x reference)
#include <cuda_runtime.h>
#include <cuda_fp16.h>

// Swin window attention: one CTA per PAIR of horizontally-adjacent 8x8 windows.
// R16 structure + LDG.128-packed fragment tables + QKV bias as MMA C-init.
// Single-pass V fragments; 64B-coalesced global in/out; tables L1-resident (4 CTAs/SM).
// Q never touches smem; max-free half2 softmax (log2-domain); rel-pos bias as C-init;
// row sums via ones-column MMA.

#define NPAIR  4096
#define TPB    256
#define LOG2E  1.4426950408889634f
#define ONESH2 0x3C003C00u

// smem layout (bytes)
#define OFF_XN   0        // half [128][72] 18432  (Z both windows; later AO)
#define OFF_KV   18432    // half [64][136] K|V per window (17408) / staging [128][72]
#define SMEM_BYTES 36864

// pre-baked tables (prep kernel fills these) — all packed for lane-contiguous LDG.128
__device__ uint4 g_qfrag4[4 * 4 * 32];        // [h][kt][lane]    : ntiles 2h,2h+1
__device__ uint4 g_kvfrag4[4 * 4 * 32 * 2];   // [h][kt][lane][2] : ntiles 8+4h..11+4h
__device__ uint4 g_pfrag4[4 * 4 * 32];        // [p][kt][lane]    : proj ntiles 2p,2p+1
__device__ unsigned g_qkvbh[96];              // half2 qkv bias per col-pair (scale folded)
__device__ uint4 g_biasfh4[2048];             // [warp][mt][quad][lane] (lane-contiguous)

__device__ __forceinline__ unsigned packh2f(float lo, float hi) {
    __half2 h = __floats2half2_rn(lo, hi);
    return *reinterpret_cast<unsigned*>(&h);
}

__global__ void prep_kernel(const float* __restrict__ qw, const float* __restrict__ pw,
                            const float* __restrict__ nw, const float* __restrict__ nb,
                            const float* __restrict__ rpb) {
    int idx = blockIdx.x * blockDim.x + threadIdx.x;   // 32 blocks * 256 = 8192

    // helper: one 8x8-tile B-fragment pair (2 regs) for qkv weight ntile at kt
    auto qkvfrag = [&](int ntile, int kt, int lane, unsigned& f0, unsigned& f1) {
        int n  = ntile * 8 + (lane >> 2);
        int k0 = kt * 16 + (lane & 3) * 2;
        float sc = (n < 64) ? 0.25f * LOG2E : 1.0f;
        const float* wr = qw + n * 64;
        f0 = packh2f(wr[k0] * nw[k0] * sc,         wr[k0 + 1] * nw[k0 + 1] * sc);
        f1 = packh2f(wr[k0 + 8] * nw[k0 + 8] * sc, wr[k0 + 9] * nw[k0 + 9] * sc);
    };

    if (idx < 512) {   // g_qfrag4: [h][kt][lane]
        int lane = idx & 31, kt = (idx >> 5) & 3, h = idx >> 7;
        unsigned a0, a1, b0, b1;
        qkvfrag(2 * h,     kt, lane, a0, a1);
        qkvfrag(2 * h + 1, kt, lane, b0, b1);
        g_qfrag4[idx] = make_uint4(a0, a1, b0, b1);
    }
    if (idx < 1024) {  // g_kvfrag4: [h][kt][lane][2]
        int half = idx & 1, lane = (idx >> 1) & 31, kt = (idx >> 6) & 3, h = idx >> 8;
        unsigned a0, a1, b0, b1;
        qkvfrag(8 + 4 * h + 2 * half,     kt, lane, a0, a1);
        qkvfrag(8 + 4 * h + 2 * half + 1, kt, lane, b0, b1);
        g_kvfrag4[((h * 4 + kt) * 32 + lane) * 2 + half] = make_uint4(a0, a1, b0, b1);
    }
    if (idx < 512) {   // g_pfrag4: [p][kt][lane]
        int lane = idx & 31, kt = (idx >> 5) & 3, p = idx >> 7;
        auto pfrag = [&](int ntile, unsigned& f0, unsigned& f1) {
            int n  = ntile * 8 + (lane >> 2);
            int k0 = kt * 16 + (lane & 3) * 2;
            const float* wr = pw + n * 64;
            f0 = packh2f(wr[k0],     wr[k0 + 1]);
            f1 = packh2f(wr[k0 + 8], wr[k0 + 9]);
        };
        unsigned a0, a1, b0, b1;
        pfrag(2 * p, a0, a1);
        pfrag(2 * p + 1, b0, b1);
        g_pfrag4[idx] = make_uint4(a0, a1, b0, b1);
    }
    if (idx < 96) {    // folded LN-bias through qkv (per output col pair), scale folded
        float b0 = 0.f, b1 = 0.f;
        int c = idx * 2;
        for (int k = 0; k < 64; k++) {
            b0 += nb[k] * qw[c * 64 + k];
            b1 += nb[k] * qw[(c + 1) * 64 + k];
        }
        float sc = (c < 64) ? 0.25f * LOG2E : 1.0f;
        g_qkvbh[idx] = packh2f(b0 * sc, b1 * sc);
    }
    if (idx < 2048) {  // bias fragments: uint4 per (warp, mt, quad, lane); lane-contiguous
        int lane = idx & 31;
        int qd   = (idx >> 5) & 3;
        int mt   = (idx >> 7) & 1;
        int warp = idx >> 8;
        int h  = warp >> 1;
        int m0 = (warp & 1) * 32;
        int g  = lane >> 2, tig = lane & 3;
        int rr = m0 + mt * 16 + g;
        auto bias = [&](int r, int c) {
            int dy = (r >> 3) - (c >> 3);
            int dx = (r & 7) - (c & 7);
            return rpb[((dy + 7) * 15 + (dx + 7)) * 4 + h] * LOG2E;
        };
        int c0 = (2 * qd) * 8 + tig * 2;
        int c1 = (2 * qd + 1) * 8 + tig * 2;
        g_biasfh4[idx] = make_uint4(
            packh2f(bias(rr, c0),     bias(rr, c0 + 1)),
            packh2f(bias(rr + 8, c0), bias(rr + 8, c0 + 1)),
            packh2f(bias(rr, c1),     bias(rr, c1 + 1)),
            packh2f(bias(rr + 8, c1), bias(rr + 8, c1 + 1)));
    }
}

__device__ __forceinline__ unsigned saddr(const void* p) {
    return (unsigned)__cvta_generic_to_shared(p);
}
__device__ __forceinline__ void ldsm_x4(unsigned a, unsigned& r0, unsigned& r1, unsigned& r2, unsigned& r3) {
    asm volatile("ldmatrix.sync.aligned.m8n8.x4.shared.b16 {%0,%1,%2,%3}, [%4];"
                 : "=r"(r0), "=r"(r1), "=r"(r2), "=r"(r3) : "r"(a));
}
__device__ __forceinline__ void ldsm_x4t(unsigned a, unsigned& r0, unsigned& r1, unsigned& r2, unsigned& r3) {
    asm volatile("ldmatrix.sync.aligned.m8n8.x4.trans.shared.b16 {%0,%1,%2,%3}, [%4];"
                 : "=r"(r0), "=r"(r1), "=r"(r2), "=r"(r3) : "r"(a));
}
__device__ __forceinline__ void mmah(uint2& c, unsigned a0, unsigned a1, unsigned a2, unsigned a3,
                                     unsigned b0, unsigned b1) {
    asm volatile("mma.sync.aligned.m16n8k16.row.col.f16.f16.f16.f16 "
                 "{%0,%1}, {%2,%3,%4,%5}, {%6,%7}, {%0,%1};"
                 : "+r"(c.x), "+r"(c.y)
                 : "r"(a0), "r"(a1), "r"(a2), "r"(a3), "r"(b0), "r"(b1));
}
__device__ __forceinline__ unsigned ex2h2(unsigned a) {
    unsigned r;
    asm("ex2.approx.f16x2 %0, %1;" : "=r"(r) : "r"(a));
    return r;
}
__device__ __forceinline__ unsigned hmul2u(unsigned a, unsigned b) {
    __half2 r = __hmul2(*(__half2*)&a, *(__half2*)&b);
    return *(unsigned*)&r;
}
__device__ __forceinline__ float2 h2f2(unsigned u) {
    return __half22float2(*(__half2*)&u);
}
__device__ __forceinline__ float hlo2f(unsigned u) {
    return __half2float(__low2half(*(__half2*)&u));
}

__global__ __launch_bounds__(256, 4)
void ewa_kernel(const float* __restrict__ x,
                const float* __restrict__ ascale,
                float* __restrict__ out) {
    extern __shared__ char smem[];
    __half* XN = (__half*)(smem + OFF_XN);   // [128][72]  Z / AO (both windows)
    __half* KV = (__half*)(smem + OFF_KV);   // [64][136] K|V (per window) / staging

    const int tid  = threadIdx.x;
    const int lane = tid & 31;
    const int warp = tid >> 5;
    const int g    = lane >> 2;
    const int tig  = lane & 3;
    const int l2   = lane & 15;

    const int pid = blockIdx.x;
    const int b   = pid >> 9;
    const int rem = pid & 511;
    const int wy  = rem >> 4;      // 0..31
    const int wpx = rem & 15;      // window-pair column: px base = wpx*16

    const int h  = warp >> 1;      // head (phases 2-3)
    const int m0 = (warp & 1) * 32;

    // ---- Phase 1: 64B-coalesced load of both windows + in-register LayerNorm ----
    {
        int r    = warp;           // pixel row within window (0..7)
        int px16 = lane >> 1;      // 0..15 across the pair
        int hq   = lane & 1;       // channel half (0: c 0-31, 1: c 32-63)
        int w    = px16 >> 3;
        int tp   = w * 64 + r * 8 + (px16 & 7);    // token index in pair coords
        const float* base = x + (b * 64 + hq * 32) * 65536
                              + (wy * 8 + r) * 256 + wpx * 16 + px16;
        float v[32];
        #pragma unroll
        for (int i = 0; i < 32; i++) v[i] = base[i * 65536];
        float s = 0.f, ss = 0.f;
        #pragma unroll
        for (int i = 0; i < 32; i++) { s += v[i]; ss += v[i] * v[i]; }
        s  += __shfl_xor_sync(0xffffffffu, s, 1);
        ss += __shfl_xor_sync(0xffffffffu, ss, 1);
        float mu   = s * (1.f / 64.f);
        float var  = ss * (1.f / 64.f) - mu * mu;
        float rstd = rsqrtf(var + 1e-5f);
        unsigned hh[16];
        #pragma unroll
        for (int i = 0; i < 16; i++)
            hh[i] = packh2f((v[2 * i] - mu) * rstd, (v[2 * i + 1] - mu) * rstd);
        uint4* dst = (uint4*)(XN + tp * 72 + hq * 32);
        dst[0] = make_uint4(hh[0],  hh[1],  hh[2],  hh[3]);
        dst[1] = make_uint4(hh[4],  hh[5],  hh[6],  hh[7]);
        dst[2] = make_uint4(hh[8],  hh[9],  hh[10], hh[11]);
        dst[3] = make_uint4(hh[12], hh[13], hh[14], hh[15]);
    }
    __syncthreads();

    // ---- Phases 2+3 per window (KV buffer reused) ----
    #pragma unroll
    for (int w = 0; w < 2; w++) {
        const int rb = w * 64;     // row base in XN for this window
        unsigned qa[2][4];

        // Phase 2: QKV GEMM; Q stays in registers, K/V -> smem. Bias as C-init.
        {
            unsigned bq0 = g_qkvbh[h * 8 + tig];
            unsigned bq1 = g_qkvbh[h * 8 + 4 + tig];
            uint2 qacc[2][2], kvacc[2][4];
            #pragma unroll
            for (int mt = 0; mt < 2; mt++) {
                qacc[mt][0] = make_uint2(bq0, bq0);
                qacc[mt][1] = make_uint2(bq1, bq1);
                #pragma unroll
                for (int j = 0; j < 4; j++) {
                    unsigned bh = g_qkvbh[32 + h * 16 + j * 4 + tig];
                    kvacc[mt][j] = make_uint2(bh, bh);
                }
            }
            #pragma unroll
            for (int kt = 0; kt < 4; kt++) {
                unsigned a[2][4];
                #pragma unroll
                for (int mt = 0; mt < 2; mt++)
                    ldsm_x4(saddr(XN + (rb + m0 + mt * 16 + l2) * 72 + kt * 16 + (lane >> 4) * 8),
                            a[mt][0], a[mt][1], a[mt][2], a[mt][3]);
                uint4 qb = g_qfrag4[(h * 4 + kt) * 32 + lane];
                uint4 kv0 = g_kvfrag4[((h * 4 + kt) * 32 + lane) * 2];
                uint4 kv1 = g_kvfrag4[((h * 4 + kt) * 32 + lane) * 2 + 1];
                #pragma unroll
                for (int mt = 0; mt < 2; mt++) {
                    mmah(qacc[mt][0], a[mt][0], a[mt][1], a[mt][2], a[mt][3], qb.x, qb.y);
                    mmah(qacc[mt][1], a[mt][0], a[mt][1], a[mt][2], a[mt][3], qb.z, qb.w);
                    mmah(kvacc[mt][0], a[mt][0], a[mt][1], a[mt][2], a[mt][3], kv0.x, kv0.y);
                    mmah(kvacc[mt][1], a[mt][0], a[mt][1], a[mt][2], a[mt][3], kv0.z, kv0.w);
                    mmah(kvacc[mt][2], a[mt][0], a[mt][1], a[mt][2], a[mt][3], kv1.x, kv1.y);
                    mmah(kvacc[mt][3], a[mt][0], a[mt][1], a[mt][2], a[mt][3], kv1.z, kv1.w);
                }
            }
            // Q: D-frag == A-frag for QK^T (bias already in)
            #pragma unroll
            for (int mt = 0; mt < 2; mt++) {
                qa[mt][0] = qacc[mt][0].x;
                qa[mt][1] = qacc[mt][0].y;
                qa[mt][2] = qacc[mt][1].x;
                qa[mt][3] = qacc[mt][1].y;
            }
            // K/V -> smem (smem col = global col - 64)
            #pragma unroll
            for (int j = 0; j < 4; j++) {
                int col = h * 32 + j * 8 + tig * 2;
                #pragma unroll
                for (int mt = 0; mt < 2; mt++) {
                    int row = m0 + mt * 16 + g;
                    *(unsigned*)(KV + row * 136 + col)       = kvacc[mt][j].x;
                    *(unsigned*)(KV + (row + 8) * 136 + col) = kvacc[mt][j].y;
                }
            }
        }
        __syncthreads();

        // Phase 3: attention. QK^T for BOTH mt tiles first, then V loaded once per kt.
        {
            const uint4* bfp = g_biasfh4 + (warp * 2) * 128 + lane;
            uint2 s0[8], s1[8];
            #pragma unroll
            for (int qd = 0; qd < 4; qd++) {
                uint4 b0 = bfp[qd * 32];
                uint4 b1 = bfp[128 + qd * 32];
                s0[2 * qd].x = b0.x;     s0[2 * qd].y = b0.y;
                s0[2 * qd + 1].x = b0.z; s0[2 * qd + 1].y = b0.w;
                s1[2 * qd].x = b1.x;     s1[2 * qd].y = b1.y;
                s1[2 * qd + 1].x = b1.z; s1[2 * qd + 1].y = b1.w;
            }

            unsigned kb[8][2];
            #pragma unroll
            for (int jp = 0; jp < 4; jp++) {
                unsigned r0, r1, r2, r3;
                int j  = (lane >> 4);
                int kh = (lane >> 3) & 1;
                ldsm_x4(saddr(KV + ((jp * 2 + j) * 8 + (lane & 7)) * 136 + h * 16 + kh * 8),
                        r0, r1, r2, r3);
                kb[jp * 2 + 0][0] = r0; kb[jp * 2 + 0][1] = r1;
                kb[jp * 2 + 1][0] = r2; kb[jp * 2 + 1][1] = r3;
            }

            #pragma unroll
            for (int j = 0; j < 8; j++) {
                mmah(s0[j], qa[0][0], qa[0][1], qa[0][2], qa[0][3], kb[j][0], kb[j][1]);
                mmah(s1[j], qa[1][0], qa[1][1], qa[1][2], qa[1][3], kb[j][0], kb[j][1]);
            }

            #pragma unroll
            for (int j = 0; j < 8; j++) {
                s0[j].x = ex2h2(s0[j].x);  s0[j].y = ex2h2(s0[j].y);
                s1[j].x = ex2h2(s1[j].x);  s1[j].y = ex2h2(s1[j].y);
            }

            // AV + row sums: V fragments loaded ONCE per kt, feeding both mts
            uint2 o0[2], o1[2], z0, z1;
            o0[0] = make_uint2(0u, 0u); o0[1] = make_uint2(0u, 0u);
            o1[0] = make_uint2(0u, 0u); o1[1] = make_uint2(0u, 0u);
            z0 = make_uint2(0u, 0u);    z1 = make_uint2(0u, 0u);
            #pragma unroll
            for (int kt = 0; kt < 4; kt++) {
                unsigned v0, v1, v2, v3;
                ldsm_x4t(saddr(KV + (kt * 16 + (lane & 7) + ((lane >> 3) & 1) * 8) * 136
                               + 64 + h * 16 + (lane >> 4) * 8),
                         v0, v1, v2, v3);
                mmah(o0[0], s0[2 * kt].x, s0[2 * kt].y, s0[2 * kt + 1].x, s0[2 * kt + 1].y, v0, v1);
                mmah(o0[1], s0[2 * kt].x, s0[2 * kt].y, s0[2 * kt + 1].x, s0[2 * kt + 1].y, v2, v3);
                mmah(o1[0], s1[2 * kt].x, s1[2 * kt].y, s1[2 * kt + 1].x, s1[2 * kt + 1].y, v0, v1);
                mmah(o1[1], s1[2 * kt].x, s1[2 * kt].y, s1[2 * kt + 1].x, s1[2 * kt + 1].y, v2, v3);
                mmah(z0, s0[2 * kt].x, s0[2 * kt].y, s0[2 * kt + 1].x, s0[2 * kt + 1].y,
                     ONESH2, ONESH2);
                mmah(z1, s1[2 * kt].x, s1[2 * kt].y, s1[2 * kt + 1].x, s1[2 * kt + 1].y,
                     ONESH2, ONESH2);
            }

            float f00 = __fdividef(1.f, hlo2f(z0.x));
            float f01 = __fdividef(1.f, hlo2f(z0.y));
            float f10 = __fdividef(1.f, hlo2f(z1.x));
            float f11 = __fdividef(1.f, hlo2f(z1.y));
            unsigned i00 = packh2f(f00, f00), i01 = packh2f(f01, f01);
            unsigned i10 = packh2f(f10, f10), i11 = packh2f(f11, f11);
            #pragma unroll
            for (int nt = 0; nt < 2; nt++) {
                int col = h * 16 + nt * 8 + tig * 2;
                int r0 = rb + m0 + g;
                int r1 = rb + m0 + 16 + g;
                *(unsigned*)(XN + r0 * 72 + col)        = hmul2u(o0[nt].x, i00);
                *(unsigned*)(XN + (r0 + 8) * 72 + col)  = hmul2u(o0[nt].y, i01);
                *(unsigned*)(XN + r1 * 72 + col)        = hmul2u(o1[nt].x, i10);
                *(unsigned*)(XN + (r1 + 8) * 72 + col)  = hmul2u(o1[nt].y, i11);
            }
        }
        __syncthreads();
    }

    // ---- Phase 4: proj GEMM both windows, stage fp16 results into KV buffer ----
    {
        const int p = warp >> 1;       // ntile pair (2p, 2p+1)
        uint4 bf[4];
        #pragma unroll
        for (int kt = 0; kt < 4; kt++)
            bf[kt] = g_pfrag4[(p * 4 + kt) * 32 + lane];

        #pragma unroll
        for (int w = 0; w < 2; w++) {
            const int rb = w * 64;
            uint2 acc[2][2];
            acc[0][0] = make_uint2(0u, 0u); acc[0][1] = make_uint2(0u, 0u);
            acc[1][0] = make_uint2(0u, 0u); acc[1][1] = make_uint2(0u, 0u);
            #pragma unroll
            for (int kt = 0; kt < 4; kt++) {
                unsigned a[2][4];
                #pragma unroll
                for (int mt = 0; mt < 2; mt++)
                    ldsm_x4(saddr(XN + (rb + m0 + mt * 16 + l2) * 72 + kt * 16 + (lane >> 4) * 8),
                            a[mt][0], a[mt][1], a[mt][2], a[mt][3]);
                #pragma unroll
                for (int mt = 0; mt < 2; mt++) {
                    mmah(acc[mt][0], a[mt][0], a[mt][1], a[mt][2], a[mt][3], bf[kt].x, bf[kt].y);
                    mmah(acc[mt][1], a[mt][0], a[mt][1], a[mt][2], a[mt][3], bf[kt].z, bf[kt].w);
                }
            }
            // stage fp16 proj results: KV reused as [128][72]
            #pragma unroll
            for (int mt = 0; mt < 2; mt++)
                #pragma unroll
                for (int nt = 0; nt < 2; nt++) {
                    int row = w * 64 + m0 + mt * 16 + g;
                    int col = (p * 2 + nt) * 8 + tig * 2;
                    *(unsigned*)(KV + row * 72 + col)       = acc[mt][nt].x;
                    *(unsigned*)(KV + (row + 8) * 72 + col) = acc[mt][nt].y;
                }
        }
    }
    __syncthreads();

    // ---- Epilogue: 64B-coalesced residual read-modify-write ----
    {
        int r    = warp;
        int px16 = lane >> 1;
        int hq   = lane & 1;
        int w    = px16 >> 3;
        int tp   = w * 64 + r * 8 + (px16 & 7);
        const uint4* src = (const uint4*)(KV + tp * 72 + hq * 32);
        uint4 u0 = src[0], u1 = src[1], u2 = src[2], u3 = src[3];
        unsigned hv[16] = {u0.x, u0.y, u0.z, u0.w, u1.x, u1.y, u1.z, u1.w,
                           u2.x, u2.y, u2.z, u2.w, u3.x, u3.y, u3.z, u3.w};
        float ssc = ascale[0];
        int gi = (b * 64 + hq * 32) * 65536 + (wy * 8 + r) * 256 + wpx * 16 + px16;
        #pragma unroll
        for (int i = 0; i < 16; i++) {
            float2 pv = h2f2(hv[i]);
            out[gi]         = x[gi]         + ssc * pv.x;   // channel hq*32 + 2i
            out[gi + 65536] = x[gi + 65536] + ssc * pv.y;   // channel hq*32 + 2i + 1
            gi += 2 * 65536;
        }
    }
}

extern "C" void kernel_launch(void* const* d_in, const int* in_sizes, int n_in,
                              void* d_out, int out_size) {
    const float* x  = (const float*)d_in[0];
    const float* nw = (const float*)d_in[1];
    const float* nb = (const float*)d_in[2];
    const float* qw = (const float*)d_in[3];
    const float* pw = (const float*)d_in[4];
    const float* sc = (const float*)d_in[5];
    const float* rp = (const float*)d_in[6];
    float* out = (float*)d_out;

    cudaFuncSetAttribute(ewa_kernel, cudaFuncAttributeMaxDynamicSharedMemorySize, SMEM_BYTES);

    prep_kernel<<<32, 256>>>(qw, pw, nw, nb, rp);
    ewa_kernel<<<NPAIR, TPB, SMEM_BYTES>>>(x, sc, out);
}